// round 13
// baseline (speedup 1.0000x reference)
#include <cuda_runtime.h>
#include <cstdint>
#include <cstddef>

#define BATCH 8
#define P 2048
#define D 64
#define FEPS 0.1f
// log2(e)/eps
#define INV 14.426950408889634f
// eps*ln(2)
#define EPSLN2 0.06931471805599453f
#define NMAT ((size_t)BATCH * P * P)
#define NBLK 148             // persistent blocks (1 per SM)
#define TILE_BYTES 65536u    // 8 rows * 2048 * 4B
#define NSTAGE 3
#define GATE 30.0f
#define TPB_F 512

// ---------------- scratch (static device globals; no runtime allocation) ----
__device__ __align__(16) float g_u[BATCH * P];
__device__ __align__(16) float g_v[BATCH * P];
__device__ float g_xn[BATCH * P];
__device__ float g_yn[BATCH * P];
__device__ float g_errp[BATCH * P];            // per-row |du|
__device__ float g_costp[BATCH * P];
__device__ int   g_done[2];                    // parity double-buffered freeze flag
__device__ __align__(16) float2 g_ms[NBLK * P]; // per-block column partials (m,s)

__device__ __forceinline__ float ex2f(float x) {
    float r; asm("ex2.approx.f32 %0, %1;" : "=f"(r) : "f"(x)); return r;
}
__device__ __forceinline__ float lg2f_(float x) {
    float r; asm("lg2.approx.f32 %0, %1;" : "=f"(r) : "f"(x)); return r;
}
__device__ __forceinline__ float eps_log_marginal() {
    return FEPS * logf(1.0f / 2048.0f + 1e-8f);
}
__device__ __forceinline__ uint32_t smem_u32(const void* p) {
    return (uint32_t)__cvta_generic_to_shared(p);
}
__device__ __forceinline__ void mbar_wait(uint32_t mbar, uint32_t phase) {
    asm volatile(
        "{\n\t.reg .pred P;\n\t"
        "W%=: mbarrier.try_wait.parity.acquire.cta.shared::cta.b64 P, [%0], %1;\n\t"
        "@!P bra W%=;\n\t}"
        :: "r"(mbar), "r"(phase) : "memory");
}
__device__ __forceinline__ void issue_copy(uint32_t smem_dst, const void* src, uint32_t mbar) {
    asm volatile("mbarrier.arrive.expect_tx.shared.b64 _, [%0], %1;"
                 :: "r"(mbar), "r"(TILE_BYTES) : "memory");
    asm volatile("cp.async.bulk.shared::cta.global.mbarrier::complete_tx::bytes "
                 "[%0], [%1], %2, [%3];"
                 :: "r"(smem_dst), "l"(src), "r"(TILE_BYTES), "r"(mbar) : "memory");
}

// ---------------- init --------------------------------------------------------
__global__ void k_init() {
    int i = blockIdx.x * blockDim.x + threadIdx.x;
    if (i < BATCH * P) { g_u[i] = 0.0f; g_v[i] = 0.0f; }
    if (i == 0) { g_done[0] = 0; g_done[1] = 0; }
}

// ---------------- squared norms (warp per point) ------------------------------
__global__ void k_norm(const float* __restrict__ x, const float* __restrict__ y) {
    int gw   = (blockIdx.x * blockDim.x + threadIdx.x) >> 5;
    int lane = threadIdx.x & 31;
    if (gw >= 2 * BATCH * P) return;
    bool isx = gw < BATCH * P;
    int p = isx ? gw : gw - BATCH * P;
    const float* src = isx ? x : y;
    float a0 = src[(size_t)p * D + lane];
    float a1 = src[(size_t)p * D + 32 + lane];
    float s = a0 * a0 + a1 * a1;
    #pragma unroll
    for (int o = 16; o; o >>= 1) s += __shfl_xor_sync(0xffffffffu, s, o);
    if (lane == 0) (isx ? g_xn : g_yn)[p] = s;
}

// ---------------- C = ||x||^2 + ||y||^2 - 2 x.y (row-major only) --------------
__global__ void k_costmat(const float* __restrict__ x, const float* __restrict__ y,
                          float* __restrict__ Cout) {
    __shared__ float xs[64][65];
    __shared__ float ys[64][65];
    int b  = blockIdx.z;
    int i0 = blockIdx.y * 64;
    int j0 = blockIdx.x * 64;
    int tid = threadIdx.x;

    const float* xb = x + ((size_t)b * P + i0) * D;
    const float* yb = y + ((size_t)b * P + j0) * D;
    #pragma unroll
    for (int idx = tid; idx < 4096; idx += 256) {
        int p = idx >> 6, d = idx & 63;
        xs[d][p] = xb[(size_t)p * D + d];
        ys[d][p] = yb[(size_t)p * D + d];
    }
    __syncthreads();

    int tx = tid & 15, ty = tid >> 4;
    float acc[4][4];
    #pragma unroll
    for (int r = 0; r < 4; r++)
        #pragma unroll
        for (int c = 0; c < 4; c++) acc[r][c] = 0.0f;

    #pragma unroll 8
    for (int k = 0; k < 64; k++) {
        float rx[4], ry[4];
        #pragma unroll
        for (int r = 0; r < 4; r++) rx[r] = xs[k][ty * 4 + r];
        #pragma unroll
        for (int c = 0; c < 4; c++) ry[c] = ys[k][tx * 4 + c];
        #pragma unroll
        for (int r = 0; r < 4; r++)
            #pragma unroll
            for (int c = 0; c < 4; c++) acc[r][c] = fmaf(rx[r], ry[c], acc[r][c]);
    }

    float xnr[4], ynr[4];
    #pragma unroll
    for (int r = 0; r < 4; r++) xnr[r] = g_xn[b * P + i0 + ty * 4 + r];
    #pragma unroll
    for (int c = 0; c < 4; c++) ynr[c] = g_yn[b * P + j0 + tx * 4 + c];

    #pragma unroll
    for (int r = 0; r < 4; r++) {
        int row = i0 + ty * 4 + r;
        float4 v4;
        v4.x = xnr[r] + ynr[0] - 2.0f * acc[r][0];
        v4.y = xnr[r] + ynr[1] - 2.0f * acc[r][1];
        v4.z = xnr[r] + ynr[2] - 2.0f * acc[r][2];
        v4.w = xnr[r] + ynr[3] - 2.0f * acc[r][3];
        *reinterpret_cast<float4*>(Cout + ((size_t)b * P + row) * P + j0 + tx * 4) = v4;
    }
}

// ---------------- fused u+v streaming pass ------------------------------------
// One stream of C per iteration. Per 8-row tile: exact u-LSE (R10 layout,
// 2 warps/row), then online column-LSE into per-block (m_col,s_col), exp2
// gated per warp. Blocks are partitioned per batch; partials flushed to g_ms.
__global__ void __launch_bounds__(TPB_F, 1) k_fused(const float* __restrict__ Cg, int par) {
    if (g_done[par]) return;

    int blk = blockIdx.x;
    int b = 0;
    while (((b + 1) * NBLK) / BATCH <= blk) b++;
    int i0b = (b * NBLK) / BATCH;
    int nb  = ((b + 1) * NBLK) / BATCH - i0b;
    int li  = blk - i0b;
    int t0  = (li * 256) / nb;          // 8-row tiles within batch b
    int t1  = ((li + 1) * 256) / nb;

    extern __shared__ __align__(128) float tile[];      // NSTAGE * 16384 floats
    __shared__ float mcol[P];
    __shared__ float scol[P];
    __shared__ float un[8];       // u_new * INV for current tile rows
    __shared__ float sm[16];
    __shared__ float ss[16];
    __shared__ __align__(8) unsigned long long mbars[NSTAGE];

    int tid = threadIdx.x, lane = tid & 31, warp = tid >> 5;
    int row8 = warp >> 1;
    int half = warp & 1;

    uint32_t mb0 = smem_u32(&mbars[0]);
    if (tid == 0) {
        #pragma unroll
        for (int s = 0; s < NSTAGE; s++)
            asm volatile("mbarrier.init.shared.b64 [%0], 1;" :: "r"(mb0 + 8 * s) : "memory");
    }
    #pragma unroll
    for (int c = 0; c < 4; c++) {
        mcol[tid * 4 + c] = -3.4e38f;
        scol[tid * 4 + c] = 0.0f;
    }
    __syncthreads();
    if (tid == 0) {
        #pragma unroll
        for (int s = 0; s < NSTAGE; s++)
            if (t0 + s < t1)
                issue_copy(smem_u32(tile) + s * TILE_BYTES,
                           Cg + ((size_t)b * P + (size_t)(t0 + s) * 8) * P, mb0 + 8 * s);
    }

    // dual vector v * INV in registers (R10 layout: half-row, lane-strided)
    float4 tv[8];
    {
        const float4* vb4 = reinterpret_cast<const float4*>(g_v + b * P);
        #pragma unroll
        for (int q = 0; q < 8; q++) {
            float4 t = vb4[half * 256 + lane + 32 * q];
            tv[q] = make_float4(t.x * INV, t.y * INV, t.z * INV, t.w * INV);
        }
    }

    int phase[NSTAGE];
    #pragma unroll
    for (int s = 0; s < NSTAGE; s++) phase[s] = 0;

    for (int k = t0; k < t1; k++) {
        int s = (k - t0) % NSTAGE;
        mbar_wait(mb0 + 8 * s, (uint32_t)phase[s]);
        phase[s] ^= 1;

        const float4* R = reinterpret_cast<const float4*>(tile + s * 16384)
                          + row8 * 512 + half * 256;

        // ---- u-phase pass 1: half-row max ----
        float lm = -3.4e38f;
        #pragma unroll
        for (int q = 0; q < 8; q++) {
            float4 c = R[lane + q * 32];
            float4 t = tv[q];
            lm = fmaxf(lm, fmaf(c.x, -INV, t.x));
            lm = fmaxf(lm, fmaf(c.y, -INV, t.y));
            lm = fmaxf(lm, fmaf(c.z, -INV, t.z));
            lm = fmaxf(lm, fmaf(c.w, -INV, t.w));
        }
        float mh = lm;
        #pragma unroll
        for (int o = 16; o; o >>= 1) mh = fmaxf(mh, __shfl_xor_sync(0xffffffffu, mh, o));
        if (lane == 0) sm[warp] = mh;
        __syncthreads();   // B1

        float m = fmaxf(sm[warp], sm[warp ^ 1]);

        // ---- u-phase pass 2: gated exp2 sum ----
        float ls = 0.0f;
        if (lm > m - GATE) {
            #pragma unroll
            for (int q = 0; q < 8; q++) {
                float4 c = R[lane + q * 32];
                float4 t = tv[q];
                ls += ex2f(fmaf(c.x, -INV, t.x) - m);
                ls += ex2f(fmaf(c.y, -INV, t.y) - m);
                ls += ex2f(fmaf(c.z, -INV, t.z) - m);
                ls += ex2f(fmaf(c.w, -INV, t.w) - m);
            }
        }
        #pragma unroll
        for (int o = 16; o; o >>= 1) ls += __shfl_xor_sync(0xffffffffu, ls, o);
        if (lane == 0) ss[warp] = ls;
        __syncthreads();   // B2

        if (half == 0 && lane == 0) {
            float tot = ss[warp] + ss[warp | 1];
            float nv = eps_log_marginal() - EPSLN2 * (m + lg2f_(tot));
            int r = b * P + k * 8 + row8;
            float old = g_u[r];
            g_u[r] = nv;
            g_errp[r] = fabsf(nv - old);
            un[row8] = nv * INV;
        }
        __syncthreads();   // B3: un visible

        // ---- column-phase: online LSE over this tile's 8 rows ----
        float ui[8];
        #pragma unroll
        for (int r = 0; r < 8; r++) ui[r] = un[r];

        const float4* T = reinterpret_cast<const float4*>(tile + s * 16384);
        int cw = warp * 32 + lane;          // float4 column-group index (4 cols)
        float4 wr[8];
        #pragma unroll
        for (int r = 0; r < 8; r++) {
            float4 c = T[r * 512 + cw];
            wr[r].x = fmaf(c.x, -INV, ui[r]);
            wr[r].y = fmaf(c.y, -INV, ui[r]);
            wr[r].z = fmaf(c.z, -INV, ui[r]);
            wr[r].w = fmaf(c.w, -INV, ui[r]);
        }
        float4 tm = wr[0];
        #pragma unroll
        for (int r = 1; r < 8; r++) {
            tm.x = fmaxf(tm.x, wr[r].x);
            tm.y = fmaxf(tm.y, wr[r].y);
            tm.z = fmaxf(tm.z, wr[r].z);
            tm.w = fmaxf(tm.w, wr[r].w);
        }
        float4 mc4 = reinterpret_cast<const float4*>(mcol)[cw];
        float4 sc4 = reinterpret_cast<const float4*>(scol)[cw];
        bool act = (tm.x > mc4.x - GATE) | (tm.y > mc4.y - GATE)
                 | (tm.z > mc4.z - GATE) | (tm.w > mc4.w - GATE);
        if (__any_sync(0xffffffffu, act)) {
            #define COLUPD(CMP) do { \
                float tmv = tm.CMP, mcv = mc4.CMP, scv = sc4.CMP; \
                if (tmv > mcv) { \
                    float a = 0.0f; \
                    _Pragma("unroll") \
                    for (int r = 0; r < 8; r++) a += ex2f(wr[r].CMP - tmv); \
                    scv = scv * ex2f(mcv - tmv) + a; \
                    mcv = tmv; \
                } else if (tmv > mcv - GATE) { \
                    float a = 0.0f; \
                    _Pragma("unroll") \
                    for (int r = 0; r < 8; r++) a += ex2f(wr[r].CMP - mcv); \
                    scv += a; \
                } \
                mc4.CMP = mcv; sc4.CMP = scv; \
            } while (0)
            COLUPD(x); COLUPD(y); COLUPD(z); COLUPD(w);
            #undef COLUPD
            reinterpret_cast<float4*>(mcol)[cw] = mc4;
            reinterpret_cast<float4*>(scol)[cw] = sc4;
        }
        __syncthreads();   // B4: all reads of stage s complete

        if (tid == 0 && k + NSTAGE < t1)
            issue_copy(smem_u32(tile) + s * TILE_BYTES,
                       Cg + ((size_t)b * P + (size_t)(k + NSTAGE) * 8) * P, mb0 + 8 * s);
    }

    // flush column partials
    #pragma unroll
    for (int c = 0; c < 4; c++) {
        int j = tid * 4 + c;
        g_ms[blk * P + j] = make_float2(mcol[j], scol[j]);
    }
}

// ---------------- combine: v update + convergence fold ------------------------
__global__ void __launch_bounds__(256) k_comb(int par) {
    if (g_done[par]) {
        if (blockIdx.x == 0 && threadIdx.x == 0) g_done[par ^ 1] = 1;
        return;
    }
    int tid = threadIdx.x;
    int idx = blockIdx.x * 256 + tid;     // b*P + j
    int b = idx >> 11;
    int j = idx & (P - 1);
    int i0 = (b * NBLK) / BATCH;
    int i1 = ((b + 1) * NBLK) / BATCH;

    float2 pp[19];
    #pragma unroll
    for (int t = 0; t < 19; t++)
        pp[t] = (i0 + t < i1) ? g_ms[(i0 + t) * P + j] : make_float2(-3.4e38f, 0.0f);

    float m = -3.4e38f, s = 0.0f;
    #pragma unroll
    for (int t = 0; t < 19; t++) {
        float mi = pp[t].x, si = pp[t].y;
        if (mi > m) { s = s * ex2f(m - mi) + si; m = mi; }
        else        { s += si * ex2f(mi - m); }
    }
    g_v[idx] = eps_log_marginal() - EPSLN2 * (m + lg2f_(s));

    if (blockIdx.x == 0) {
        __shared__ float red[8];
        float e = 0.0f;
        for (int t = tid; t < BATCH * P; t += 256) e += g_errp[t];
        #pragma unroll
        for (int o = 16; o; o >>= 1) e += __shfl_xor_sync(0xffffffffu, e, o);
        if ((tid & 31) == 0) red[tid >> 5] = e;
        __syncthreads();
        if (tid == 0) {
            float tot = 0.0f;
            #pragma unroll
            for (int i2 = 0; i2 < 8; i2++) tot += red[i2];
            g_done[par ^ 1] = (tot * (1.0f / BATCH) < 0.1f) ? 1 : 0;
        }
    }
}

// ---------------- pi = exp((u+v-C)/eps), partial cost -------------------------
__global__ void __launch_bounds__(256) k_pi(const float4* __restrict__ C4,
                                            float4* __restrict__ pi4) {
    __shared__ __align__(16) float uvw[2048];
    __shared__ float sacc[256];
    int r = blockIdx.x, b = r >> 11, tid = threadIdx.x;
    float ug = g_u[r] * INV;
    for (int j = tid; j < 2048; j += 256) uvw[j] = fmaf(g_v[b * P + j], INV, ug);
    __syncthreads();

    const float4* Crow = C4 + (size_t)r * 512;
    float4* prow = pi4 + (size_t)r * 512;
    const float4* uvw4 = reinterpret_cast<const float4*>(uvw);
    float acc = 0.0f;
    #pragma unroll 2
    for (int j4 = tid; j4 < 512; j4 += 256) {
        float4 c = Crow[j4];
        float4 t = uvw4[j4];
        float4 p;
        p.x = ex2f(fmaf(c.x, -INV, t.x));
        p.y = ex2f(fmaf(c.y, -INV, t.y));
        p.z = ex2f(fmaf(c.z, -INV, t.z));
        p.w = ex2f(fmaf(c.w, -INV, t.w));
        prow[j4] = p;
        acc = fmaf(p.x, c.x, fmaf(p.y, c.y, fmaf(p.z, c.z, fmaf(p.w, c.w, acc))));
    }
    sacc[tid] = acc;
    __syncthreads();
    for (int o = 128; o; o >>= 1) {
        if (tid < o) sacc[tid] += sacc[tid + o];
        __syncthreads();
    }
    if (tid == 0) g_costp[r] = sacc[0];
}

__global__ void k_costred(float* __restrict__ costOut) {
    __shared__ float sb[256];
    int b = blockIdx.x;
    float e = 0.0f;
    for (int t = threadIdx.x; t < P; t += 256) e += g_costp[b * P + t];
    sb[threadIdx.x] = e;
    __syncthreads();
    for (int o = 128; o; o >>= 1) {
        if (threadIdx.x < o) sb[threadIdx.x] += sb[threadIdx.x + o];
        __syncthreads();
    }
    if (threadIdx.x == 0) costOut[b] = sb[0];
}

// ---------------- launch ------------------------------------------------------
extern "C" void kernel_launch(void* const* d_in, const int* in_sizes, int n_in,
                              void* d_out, int out_size) {
    (void)in_sizes; (void)n_in; (void)out_size;
    const float* x = (const float*)d_in[0];
    const float* y = (const float*)d_in[1];
    float* out  = (float*)d_out;
    float* cost = out;                      // [8]
    float* pi   = out + 8;                  // [8,2048,2048]
    float* Cm   = out + 8 + NMAT;           // [8,2048,2048]

    cudaFuncSetAttribute(k_fused,
                         cudaFuncAttributeMaxDynamicSharedMemorySize, NSTAGE * (int)TILE_BYTES);

    k_init<<<64, 256>>>();
    k_norm<<<4096, 256>>>(x, y);
    dim3 cg(32, 32, 8);
    k_costmat<<<cg, 256>>>(x, y, Cm);

    for (int k = 0; k < 100; k++) {
        int par = k & 1;
        k_fused<<<NBLK, TPB_F, NSTAGE * TILE_BYTES>>>(Cm, par);  // u + v partials
        k_comb<<<64, 256>>>(par);                                // v + done
    }

    k_pi<<<16384, 256>>>((const float4*)Cm, (float4*)pi);
    k_costred<<<8, 256>>>(cost);
}

// round 14
// speedup vs baseline: 1.5712x; 1.5712x over previous
#include <cuda_runtime.h>
#include <cstdint>
#include <cstddef>

#define BATCH 8
#define P 2048
#define D 64
#define FEPS 0.1f
// log2(e)/eps
#define INV 14.426950408889634f
// eps*ln(2)
#define EPSLN2 0.06931471805599453f
#define NMAT ((size_t)BATCH * P * P)
#define NT4 4096             // 4-row tiles per pass
#define NBLK 296             // persistent blocks (2 per SM)
#define TILE_BYTES 32768u    // 4 rows * 2048 * 4B
#define NSTAGE 3
#define GATE 30.0f

// ---------------- scratch (static device globals; no runtime allocation) ----
__device__ __align__(16) float g_u[BATCH * P];
__device__ __align__(16) float g_v[BATCH * P];
__device__ float g_xn[BATCH * P];
__device__ float g_yn[BATCH * P];
__device__ float g_errp[BATCH * P];      // per-row |du|
__device__ float g_costp[BATCH * P];     // per-row pi*C partials
__device__ int   g_done[2];              // parity double-buffered freeze flag
__device__ __align__(16) float4 g_ct4[NMAT / 4];  // C transposed (134MB scratch)

__device__ __forceinline__ float ex2f(float x) {
    float r; asm("ex2.approx.f32 %0, %1;" : "=f"(r) : "f"(x)); return r;
}
__device__ __forceinline__ float lg2f_(float x) {
    float r; asm("lg2.approx.f32 %0, %1;" : "=f"(r) : "f"(x)); return r;
}
__device__ __forceinline__ float eps_log_marginal() {
    return FEPS * logf(1.0f / 2048.0f + 1e-8f);
}
__device__ __forceinline__ uint32_t smem_u32(const void* p) {
    return (uint32_t)__cvta_generic_to_shared(p);
}
__device__ __forceinline__ void mbar_wait(uint32_t mbar, uint32_t phase) {
    asm volatile(
        "{\n\t.reg .pred P;\n\t"
        "W%=: mbarrier.try_wait.parity.acquire.cta.shared::cta.b64 P, [%0], %1;\n\t"
        "@!P bra W%=;\n\t}"
        :: "r"(mbar), "r"(phase) : "memory");
}
__device__ __forceinline__ void issue_copy(uint32_t smem_dst, const void* src, uint32_t mbar) {
    asm volatile("mbarrier.arrive.expect_tx.shared.b64 _, [%0], %1;"
                 :: "r"(mbar), "r"(TILE_BYTES) : "memory");
    asm volatile("cp.async.bulk.shared::cta.global.mbarrier::complete_tx::bytes "
                 "[%0], [%1], %2, [%3];"
                 :: "r"(smem_dst), "l"(src), "r"(TILE_BYTES), "r"(mbar) : "memory");
}

// ---------------- init --------------------------------------------------------
__global__ void k_init() {
    int i = blockIdx.x * blockDim.x + threadIdx.x;
    if (i < BATCH * P) { g_u[i] = 0.0f; g_v[i] = 0.0f; }
    if (i == 0) { g_done[0] = 0; g_done[1] = 0; }
}

// ---------------- squared norms (warp per point) ------------------------------
__global__ void k_norm(const float* __restrict__ x, const float* __restrict__ y) {
    int gw   = (blockIdx.x * blockDim.x + threadIdx.x) >> 5;
    int lane = threadIdx.x & 31;
    if (gw >= 2 * BATCH * P) return;
    bool isx = gw < BATCH * P;
    int p = isx ? gw : gw - BATCH * P;
    const float* src = isx ? x : y;
    float a0 = src[(size_t)p * D + lane];
    float a1 = src[(size_t)p * D + 32 + lane];
    float s = a0 * a0 + a1 * a1;
    #pragma unroll
    for (int o = 16; o; o >>= 1) s += __shfl_xor_sync(0xffffffffu, s, o);
    if (lane == 0) (isx ? g_xn : g_yn)[p] = s;
}

// ---------------- C = ||x||^2 + ||y||^2 - 2 x.y  (+ transposed copy) ----------
__global__ void k_costmat(const float* __restrict__ x, const float* __restrict__ y,
                          float* __restrict__ Cout) {
    __shared__ float xs[64][65];
    __shared__ float ys[64][65];
    int b  = blockIdx.z;
    int i0 = blockIdx.y * 64;
    int j0 = blockIdx.x * 64;
    int tid = threadIdx.x;

    const float* xb = x + ((size_t)b * P + i0) * D;
    const float* yb = y + ((size_t)b * P + j0) * D;
    #pragma unroll
    for (int idx = tid; idx < 4096; idx += 256) {
        int p = idx >> 6, d = idx & 63;
        xs[d][p] = xb[(size_t)p * D + d];
        ys[d][p] = yb[(size_t)p * D + d];
    }
    __syncthreads();

    int tx = tid & 15, ty = tid >> 4;
    float acc[4][4];
    #pragma unroll
    for (int r = 0; r < 4; r++)
        #pragma unroll
        for (int c = 0; c < 4; c++) acc[r][c] = 0.0f;

    #pragma unroll 8
    for (int k = 0; k < 64; k++) {
        float rx[4], ry[4];
        #pragma unroll
        for (int r = 0; r < 4; r++) rx[r] = xs[k][ty * 4 + r];
        #pragma unroll
        for (int c = 0; c < 4; c++) ry[c] = ys[k][tx * 4 + c];
        #pragma unroll
        for (int r = 0; r < 4; r++)
            #pragma unroll
            for (int c = 0; c < 4; c++) acc[r][c] = fmaf(rx[r], ry[c], acc[r][c]);
    }

    float xnr[4], ynr[4];
    #pragma unroll
    for (int r = 0; r < 4; r++) xnr[r] = g_xn[b * P + i0 + ty * 4 + r];
    #pragma unroll
    for (int c = 0; c < 4; c++) ynr[c] = g_yn[b * P + j0 + tx * 4 + c];

    float val[4][4];
    #pragma unroll
    for (int r = 0; r < 4; r++)
        #pragma unroll
        for (int c = 0; c < 4; c++)
            val[r][c] = xnr[r] + ynr[c] - 2.0f * acc[r][c];

    #pragma unroll
    for (int r = 0; r < 4; r++) {
        int row = i0 + ty * 4 + r;
        float4 v4 = make_float4(val[r][0], val[r][1], val[r][2], val[r][3]);
        *reinterpret_cast<float4*>(Cout + ((size_t)b * P + row) * P + j0 + tx * 4) = v4;
    }

    __syncthreads();
    #pragma unroll
    for (int r = 0; r < 4; r++)
        #pragma unroll
        for (int c = 0; c < 4; c++)
            xs[ty * 4 + r][tx * 4 + c] = val[r][c];
    __syncthreads();
    float* CT = (float*)g_ct4;
    #pragma unroll
    for (int idx = tid; idx < 4096; idx += 256) {
        int jj = idx >> 6, ii = idx & 63;
        CT[((size_t)b * P + (j0 + jj)) * P + (i0 + ii)] = xs[ii][jj];
    }
}

// ---------------- persistent pipelined row-LSE pass ---------------------------
// 296 blocks (2/SM), 256 threads, 2 warps per row over 4-row/32KB tiles,
// 3-stage bulk-copy pipeline per block. Two independent pipelines per SM:
// smaller barriers (8 warps) + doubled copy-in-flight duty.
template<bool UPASS>
__global__ void __launch_bounds__(256, 2) k_lse_pipe(const float* __restrict__ Cg, int par) {
    if (g_done[par]) {
        if (!UPASS && blockIdx.x == 0 && threadIdx.x == 0) g_done[par ^ 1] = 1;
        return;
    }
    const float* M    = UPASS ? Cg : (const float*)g_ct4;
    const float* wv   = UPASS ? g_v : g_u;
    float*       outv = UPASS ? g_u : g_v;

    extern __shared__ __align__(128) float tile[];      // NSTAGE * 8192 floats
    __shared__ float sm[8];       // per-half-warp max
    __shared__ float ss[8];       // per-half-warp sum
    __shared__ float red[256];
    __shared__ __align__(8) unsigned long long mbars[NSTAGE];

    int tid = threadIdx.x, lane = tid & 31, warp = tid >> 5;
    int row4 = warp >> 1;          // 0..3 : row within tile
    int half = warp & 1;           // 0/1  : which half of the row
    int t0 = (int)(((long long)blockIdx.x * NT4) / NBLK);
    int t1 = (int)(((long long)(blockIdx.x + 1) * NT4) / NBLK);

    uint32_t mb0 = smem_u32(&mbars[0]);
    if (tid == 0) {
        #pragma unroll
        for (int s = 0; s < NSTAGE; s++)
            asm volatile("mbarrier.init.shared.b64 [%0], 1;" :: "r"(mb0 + 8 * s) : "memory");
    }
    __syncthreads();
    if (tid == 0) {
        #pragma unroll
        for (int s = 0; s < NSTAGE; s++)
            if (t0 + s < t1)
                issue_copy(smem_u32(tile) + s * TILE_BYTES,
                           M + (size_t)(t0 + s) * (4 * P), mb0 + 8 * s);
    }

    // v-pass block 0: fold convergence check (g_errp complete from u-kernel)
    if (!UPASS && blockIdx.x == 0) {
        float e = 0.0f;
        for (int t = tid; t < BATCH * P; t += 256) e += g_errp[t];
        red[tid] = e;
        __syncthreads();
        for (int o = 128; o; o >>= 1) {
            if (tid < o) red[tid] += red[tid + o];
            __syncthreads();
        }
        if (tid == 0)
            g_done[par ^ 1] = (red[0] * (1.0f / BATCH) < 0.1f) ? 1 : 0;
    }

    float4 tv[8];                 // dual vector * INV : this lane's 32 j's
    int cur_b = -1;
    int phase[NSTAGE];
    #pragma unroll
    for (int s = 0; s < NSTAGE; s++) phase[s] = 0;

    for (int k = t0; k < t1; k++) {
        int b = k >> 9;                          // 512 4-row tiles per batch
        if (b != cur_b) {
            const float4* vb4 = reinterpret_cast<const float4*>(wv + b * P);
            #pragma unroll
            for (int q = 0; q < 8; q++) {
                float4 t = vb4[half * 256 + lane + 32 * q];
                tv[q] = make_float4(t.x * INV, t.y * INV, t.z * INV, t.w * INV);
            }
            cur_b = b;
        }

        int s = (k - t0) % NSTAGE;
        mbar_wait(mb0 + 8 * s, (uint32_t)phase[s]);
        phase[s] ^= 1;

        const float4* R = reinterpret_cast<const float4*>(tile + s * 8192)
                          + row4 * 512 + half * 256;

        // pass 1: max of w = v*INV - C*INV over this half-row
        float lm = -3.4e38f;
        #pragma unroll
        for (int q = 0; q < 8; q++) {
            float4 c = R[lane + q * 32];
            float4 t = tv[q];
            lm = fmaxf(lm, fmaf(c.x, -INV, t.x));
            lm = fmaxf(lm, fmaf(c.y, -INV, t.y));
            lm = fmaxf(lm, fmaf(c.z, -INV, t.z));
            lm = fmaxf(lm, fmaf(c.w, -INV, t.w));
        }
        float mh = lm;
        #pragma unroll
        for (int o = 16; o; o >>= 1) mh = fmaxf(mh, __shfl_xor_sync(0xffffffffu, mh, o));
        if (lane == 0) sm[warp] = mh;
        __syncthreads();
        float m = fmaxf(sm[warp], sm[warp ^ 1]);   // full-row max

        // pass 2: EX2 only in the half-warp(s) containing candidates
        float ls = 0.0f;
        if (lm > m - GATE) {
            #pragma unroll
            for (int q = 0; q < 8; q++) {
                float4 c = R[lane + q * 32];
                float4 t = tv[q];
                ls += ex2f(fmaf(c.x, -INV, t.x) - m);
                ls += ex2f(fmaf(c.y, -INV, t.y) - m);
                ls += ex2f(fmaf(c.z, -INV, t.z) - m);
                ls += ex2f(fmaf(c.w, -INV, t.w) - m);
            }
        }
        #pragma unroll
        for (int o = 16; o; o >>= 1) ls += __shfl_xor_sync(0xffffffffu, ls, o);
        if (lane == 0) ss[warp] = ls;
        __syncthreads();                           // all stage-s reads complete

        if (half == 0 && lane == 0) {
            float tot = ss[warp] + ss[warp | 1];
            float nv = eps_log_marginal() - EPSLN2 * (m + lg2f_(tot));
            int r = k * 4 + row4;
            if (UPASS) {
                float old = outv[r];
                outv[r] = nv;
                g_errp[r] = fabsf(nv - old);
            } else {
                outv[r] = nv;
            }
        }
        if (tid == 0 && k + NSTAGE < t1)
            issue_copy(smem_u32(tile) + s * TILE_BYTES,
                       M + (size_t)(k + NSTAGE) * (4 * P), mb0 + 8 * s);
    }
}

// ---------------- pi = exp((u+v-C)/eps), partial cost -------------------------
__global__ void __launch_bounds__(256) k_pi(const float4* __restrict__ C4,
                                            float4* __restrict__ pi4) {
    __shared__ __align__(16) float uvw[2048];
    __shared__ float sacc[256];
    int r = blockIdx.x, b = r >> 11, tid = threadIdx.x;
    float ug = g_u[r] * INV;
    for (int j = tid; j < 2048; j += 256) uvw[j] = fmaf(g_v[b * P + j], INV, ug);
    __syncthreads();

    const float4* Crow = C4 + (size_t)r * 512;
    float4* prow = pi4 + (size_t)r * 512;
    const float4* uvw4 = reinterpret_cast<const float4*>(uvw);
    float acc = 0.0f;
    #pragma unroll 2
    for (int j4 = tid; j4 < 512; j4 += 256) {
        float4 c = Crow[j4];
        float4 t = uvw4[j4];
        float4 p;
        p.x = ex2f(fmaf(c.x, -INV, t.x));
        p.y = ex2f(fmaf(c.y, -INV, t.y));
        p.z = ex2f(fmaf(c.z, -INV, t.z));
        p.w = ex2f(fmaf(c.w, -INV, t.w));
        prow[j4] = p;
        acc = fmaf(p.x, c.x, fmaf(p.y, c.y, fmaf(p.z, c.z, fmaf(p.w, c.w, acc))));
    }
    sacc[tid] = acc;
    __syncthreads();
    for (int o = 128; o; o >>= 1) {
        if (tid < o) sacc[tid] += sacc[tid + o];
        __syncthreads();
    }
    if (tid == 0) g_costp[r] = sacc[0];
}

__global__ void k_costred(float* __restrict__ costOut) {
    __shared__ float sb[256];
    int b = blockIdx.x;
    float e = 0.0f;
    for (int t = threadIdx.x; t < P; t += 256) e += g_costp[b * P + t];
    sb[threadIdx.x] = e;
    __syncthreads();
    for (int o = 128; o; o >>= 1) {
        if (threadIdx.x < o) sb[threadIdx.x] += sb[threadIdx.x + o];
        __syncthreads();
    }
    if (threadIdx.x == 0) costOut[b] = sb[0];
}

// ---------------- launch ------------------------------------------------------
extern "C" void kernel_launch(void* const* d_in, const int* in_sizes, int n_in,
                              void* d_out, int out_size) {
    (void)in_sizes; (void)n_in; (void)out_size;
    const float* x = (const float*)d_in[0];
    const float* y = (const float*)d_in[1];
    float* out  = (float*)d_out;
    float* cost = out;                      // [8]
    float* pi   = out + 8;                  // [8,2048,2048]
    float* Cm   = out + 8 + NMAT;           // [8,2048,2048]

    cudaFuncSetAttribute(k_lse_pipe<true>,
                         cudaFuncAttributeMaxDynamicSharedMemorySize, NSTAGE * (int)TILE_BYTES);
    cudaFuncSetAttribute(k_lse_pipe<false>,
                         cudaFuncAttributeMaxDynamicSharedMemorySize, NSTAGE * (int)TILE_BYTES);

    k_init<<<64, 256>>>();
    k_norm<<<4096, 256>>>(x, y);
    dim3 cg(32, 32, 8);
    k_costmat<<<cg, 256>>>(x, y, Cm);

    for (int k = 0; k < 100; k++) {
        int par = k & 1;
        k_lse_pipe<true ><<<NBLK, 256, NSTAGE * TILE_BYTES>>>(Cm, par);  // u (rows of C)
        k_lse_pipe<false><<<NBLK, 256, NSTAGE * TILE_BYTES>>>(Cm, par);  // v (rows of C^T)
    }

    k_pi<<<16384, 256>>>((const float4*)Cm, (float4*)pi);
    k_costred<<<8, 256>>>(cost);
}